// round 10
// baseline (speedup 1.0000x reference)
#include <cuda_runtime.h>
#include <cuda_fp16.h>
#include <mma.h>
#include <cstdint>

using namespace nvcuda;

#define NN 100000
#define NP 100032            // padded to multiple of 64
#define DD 128
#define EE 1600000
#define RR 4

#define SCAN_N   (RR * NN)
#define SCAN_BLK 512
#define SCAN_NBLK ((SCAN_N + SCAN_BLK - 1) / SCAN_BLK)

// ---------------- device scratch --------------------------------------------
__device__ __half  g_Yh[(size_t)RR * NP * DD]; // 4 fp16 Y buffers (102.4MB, ~L2)
__device__ float   g_h1[(size_t)NN * DD];      // layer-1 output
__device__ int     g_degout[SCAN_N];
__device__ int     g_degin[SCAN_N];
__device__ float   g_rdout[SCAN_N];
__device__ float   g_rdin[SCAN_N];
__device__ int     g_off[SCAN_N];
__device__ int     g_cur[SCAN_N];
__device__ int     g_bsum[SCAN_NBLK];
__device__ float2  g_csr[(size_t)RR * EE];     // (src bits, weight)

// ---------------- setup kernels ---------------------------------------------

__global__ void zero_deg_kernel() {
    int i = blockIdx.x * blockDim.x + threadIdx.x;
    if (i < SCAN_N) { g_degout[i] = 0; g_degin[i] = 0; }
}

__global__ void deg_kernel(const int* __restrict__ src, const int* __restrict__ dst) {
    long long i = (long long)blockIdx.x * blockDim.x + threadIdx.x;
    if (i >= (long long)RR * EE) return;
    int r = (int)(i / EE);
    atomicAdd(&g_degout[r * NN + src[i]], 1);
    atomicAdd(&g_degin[r * NN + dst[i]], 1);
}

__global__ void rsqrt_kernel() {
    int i = blockIdx.x * blockDim.x + threadIdx.x;
    if (i >= SCAN_N) return;
    g_rdout[i] = rsqrtf(fmaxf((float)g_degout[i], 1.f));
    g_rdin[i]  = rsqrtf(fmaxf((float)g_degin[i], 1.f));
}

__global__ void scan_a_kernel() {
    __shared__ int s[SCAN_BLK];
    int i = blockIdx.x * SCAN_BLK + threadIdx.x;
    s[threadIdx.x] = (i < SCAN_N) ? g_degin[i] : 0;
    __syncthreads();
    for (int d = SCAN_BLK / 2; d > 0; d >>= 1) {
        if (threadIdx.x < d) s[threadIdx.x] += s[threadIdx.x + d];
        __syncthreads();
    }
    if (threadIdx.x == 0) g_bsum[blockIdx.x] = s[0];
}

__global__ void scan_b_kernel() {
    __shared__ int s[1024];
    int t = threadIdx.x;
    s[t] = (t < SCAN_NBLK) ? g_bsum[t] : 0;
    __syncthreads();
    for (int d = 1; d < 1024; d <<= 1) {
        int v = (t >= d) ? s[t - d] : 0;
        __syncthreads();
        s[t] += v;
        __syncthreads();
    }
    if (t < SCAN_NBLK) g_bsum[t] = (t == 0) ? 0 : s[t - 1];
}

__global__ void scan_c_kernel() {
    __shared__ int s[SCAN_BLK];
    int i = blockIdx.x * SCAN_BLK + threadIdx.x;
    int v = (i < SCAN_N) ? g_degin[i] : 0;
    s[threadIdx.x] = v;
    __syncthreads();
    for (int d = 1; d < SCAN_BLK; d <<= 1) {
        int u = (threadIdx.x >= d) ? s[threadIdx.x - d] : 0;
        __syncthreads();
        s[threadIdx.x] += u;
        __syncthreads();
    }
    if (i < SCAN_N) {
        int ex = s[threadIdx.x] - v + g_bsum[blockIdx.x];
        g_off[i] = ex;
        g_cur[i] = ex;
    }
}

__global__ void fill_kernel(const int* __restrict__ src, const int* __restrict__ dst,
                            const float* __restrict__ ew) {
    long long i = (long long)blockIdx.x * blockDim.x + threadIdx.x;
    if (i >= (long long)RR * EE) return;
    int r = (int)(i / EE);
    int s = src[i], d = dst[i];
    float w = ew[i] * g_rdout[r * NN + s] * g_rdin[r * NN + d];
    int p = atomicAdd(&g_cur[r * NN + d], 1);
    g_csr[p] = make_float2(__int_as_float(s), w);
}

// ---------------- tf32x3 tensor-core GEMM: Yh_r = half(h @ W_r) --------------
// grid = (NP/64, RR): all 4 relations in one launch.
__global__ __launch_bounds__(256) void gemm_tf32_kernel(
    const float* __restrict__ h, const float* __restrict__ Wbase)
{
    __shared__ float sAh[64][20], sAl[64][20];
    __shared__ float sBh[16][132], sBl[16][132];
    __shared__ float sStage[8][16][20];          // per-warp staging (ldm=20)

    const int r = blockIdx.y;
    const float* W = Wbase + (size_t)r * DD * DD;
    const int row0 = blockIdx.x * 64;
    const int tid = threadIdx.x;
    const int wid = tid >> 5;
    const int lane = tid & 31;
    const int wr = wid & 3;
    const int wc = wid >> 2;

    wmma::fragment<wmma::accumulator, 16, 16, 8, float> acc[4];
#pragma unroll
    for (int i = 0; i < 4; i++) wmma::fill_fragment(acc[i], 0.f);

    for (int kc = 0; kc < DD; kc += 16) {
#pragma unroll
        for (int t = tid; t < 64 * 16; t += 256) {
            int rr = t >> 4, kk = t & 15;
            int n = row0 + rr;
            float a = (n < NN) ? h[(size_t)n * DD + kc + kk] : 0.f;
            float hi = wmma::__float_to_tf32(a);
            sAh[rr][kk] = hi;
            sAl[rr][kk] = wmma::__float_to_tf32(a - hi);
        }
#pragma unroll
        for (int t = tid; t < 16 * 128; t += 256) {
            int rr = t >> 7, j = t & 127;
            float b = W[(size_t)(kc + rr) * DD + j];
            float hi = wmma::__float_to_tf32(b);
            sBh[rr][j] = hi;
            sBl[rr][j] = wmma::__float_to_tf32(b - hi);
        }
        __syncthreads();

#pragma unroll
        for (int ks = 0; ks < 2; ks++) {
            wmma::fragment<wmma::matrix_a, 16, 16, 8, wmma::precision::tf32, wmma::row_major> ah, al;
            wmma::load_matrix_sync(ah, &sAh[wr * 16][ks * 8], 20);
            wmma::load_matrix_sync(al, &sAl[wr * 16][ks * 8], 20);
#pragma unroll
            for (int cg = 0; cg < 4; cg++) {
                int col = wc * 64 + cg * 16;
                wmma::fragment<wmma::matrix_b, 16, 16, 8, wmma::precision::tf32, wmma::row_major> bh, bl;
                wmma::load_matrix_sync(bh, &sBh[ks * 8][col], 132);
                wmma::load_matrix_sync(bl, &sBl[ks * 8][col], 132);
                wmma::mma_sync(acc[cg], ah, bh, acc[cg]);
                wmma::mma_sync(acc[cg], ah, bl, acc[cg]);
                wmma::mma_sync(acc[cg], al, bh, acc[cg]);
            }
        }
        __syncthreads();
    }

    const int rr = lane >> 1;
    const int cb = (lane & 1) * 8;
    __half* Yout = g_Yh + (size_t)r * NP * DD;
#pragma unroll
    for (int cg = 0; cg < 4; cg++) {
        wmma::store_matrix_sync(&sStage[wid][0][0], acc[cg], 20, wmma::mem_row_major);
        __syncwarp();
        const float* sp = &sStage[wid][rr][cb];
        __half2 h0 = __floats2half2_rn(sp[0], sp[1]);
        __half2 h1 = __floats2half2_rn(sp[2], sp[3]);
        __half2 h2 = __floats2half2_rn(sp[4], sp[5]);
        __half2 h3 = __floats2half2_rn(sp[6], sp[7]);
        int grow = row0 + wr * 16 + rr;
        int gcol = wc * 64 + cg * 16 + cb;
        __half2 pack[4] = {h0, h1, h2, h3};
        *(uint4*)(Yout + (size_t)grow * DD + gcol) = *(const uint4*)pack;
        __syncwarp();
    }
}

// ---------------- pull (all relations) + bias + relu, fused ------------------
// Warp per node; accumulate all 4 relations in registers; no g_acc.
__global__ __launch_bounds__(256) void pull_all_kernel(
    const float* __restrict__ b, float* __restrict__ out)
{
    __shared__ float bsum[DD];
    if (threadIdx.x < DD)
        bsum[threadIdx.x] = b[threadIdx.x] + b[DD + threadIdx.x]
                          + b[2 * DD + threadIdx.x] + b[3 * DD + threadIdx.x];
    __syncthreads();

    int warp = (blockIdx.x * blockDim.x + threadIdx.x) >> 5;
    int lane = threadIdx.x & 31;
    if (warp >= NN) return;
    const int co = lane * 4;

    float4 a0 = make_float4(0.f, 0.f, 0.f, 0.f);

#pragma unroll
    for (int r = 0; r < RR; r++) {
        int idx = r * NN + warp;
        const float2* eb = g_csr + g_off[idx];
        int cnt = g_degin[idx];
        const __half* Y = g_Yh + (size_t)r * NP * DD;

        for (int j = 0; j < cnt; j += 32) {
            int m = cnt - j; if (m > 32) m = 32;
            float2 er = (lane < m) ? __ldcs(&eb[j + lane]) : make_float2(0.f, 0.f);
            int si = __float_as_int(er.x);
#pragma unroll 8
            for (int k = 0; k < m; k++) {
                int s   = __shfl_sync(0xffffffffu, si, k);
                float w = __shfl_sync(0xffffffffu, er.y, k);
                uint2 rv = *(const uint2*)(Y + (size_t)s * DD + co);
                float2 f0 = __half22float2(*(__half2*)&rv.x);
                float2 f1 = __half22float2(*(__half2*)&rv.y);
                a0.x += f0.x * w; a0.y += f0.y * w; a0.z += f1.x * w; a0.w += f1.y * w;
            }
        }
    }

    float4 o;
    o.x = fmaxf(a0.x + bsum[co],     0.f);
    o.y = fmaxf(a0.y + bsum[co + 1], 0.f);
    o.z = fmaxf(a0.z + bsum[co + 2], 0.f);
    o.w = fmaxf(a0.w + bsum[co + 3], 0.f);
    *(float4*)(out + (size_t)warp * DD + co) = o;
}

// ---------------- launch ----------------------------------------------------

extern "C" void kernel_launch(void* const* d_in, const int* in_sizes, int n_in,
                              void* d_out, int out_size)
{
    const float* x   = (const float*)d_in[0];
    const int*   src = (const int*)d_in[1];
    const int*   dst = (const int*)d_in[2];
    const float* ew  = (const float*)d_in[3];
    const float* W1  = (const float*)d_in[4];
    const float* b1  = (const float*)d_in[5];
    const float* W2  = (const float*)d_in[6];
    const float* b2  = (const float*)d_in[7];
    float* out = (float*)d_out;

    const int T = 256;
    const long long RE = (long long)RR * EE;
    const int edge_blocks = (int)((RE + T - 1) / T);

    // ---- setup (graph identical for both layers) ----
    zero_deg_kernel<<<(SCAN_N + T - 1) / T, T>>>();
    deg_kernel<<<edge_blocks, T>>>(src, dst);
    rsqrt_kernel<<<(SCAN_N + T - 1) / T, T>>>();
    scan_a_kernel<<<SCAN_NBLK, SCAN_BLK>>>();
    scan_b_kernel<<<1, 1024>>>();
    scan_c_kernel<<<SCAN_NBLK, SCAN_BLK>>>();
    fill_kernel<<<edge_blocks, T>>>(src, dst, ew);

    dim3 ggrid(NP / 64, RR);
    const int pull_blocks = (NN * 32 + T - 1) / T;

    // ---- layer 1 ----
    gemm_tf32_kernel<<<ggrid, T>>>(x, W1);
    pull_all_kernel<<<pull_blocks, T>>>(b1, g_h1);

    // ---- layer 2 ----
    gemm_tf32_kernel<<<ggrid, T>>>(g_h1, W2);
    pull_all_kernel<<<pull_blocks, T>>>(b2, out);
}

// round 11
// speedup vs baseline: 1.2003x; 1.2003x over previous
#include <cuda_runtime.h>
#include <cuda_fp16.h>
#include <mma.h>
#include <cstdint>

using namespace nvcuda;

#define NN 100000
#define NP 100032            // padded to multiple of 64
#define DD 128
#define EE 1600000
#define RR 4

#define SCAN_N   (RR * NN)
#define SCAN_BLK 512
#define SCAN_NBLK ((SCAN_N + SCAN_BLK - 1) / SCAN_BLK)

// ---------------- device scratch --------------------------------------------
__device__ __half  g_Yh[(size_t)NP * DD];      // transformed feats (fp16, 25.6MB)
__device__ float   g_h1[(size_t)NN * DD];      // layer-1 output
__device__ float   g_acc[(size_t)NN * DD];     // aggregation accumulator
__device__ int     g_degout[SCAN_N];
__device__ int     g_degin[SCAN_N];
__device__ float   g_rdout[SCAN_N];
__device__ float   g_rdin[SCAN_N];
__device__ int     g_off[SCAN_N];
__device__ int     g_cur[SCAN_N];
__device__ int     g_bsum[SCAN_NBLK];
__device__ float2  g_csr[(size_t)RR * EE];     // (src bits, weight)

// ---------------- setup kernels ---------------------------------------------

__global__ void zero_deg_kernel() {
    int i = blockIdx.x * blockDim.x + threadIdx.x;
    if (i < SCAN_N) { g_degout[i] = 0; g_degin[i] = 0; }
}

__global__ void deg_kernel(const int* __restrict__ src, const int* __restrict__ dst) {
    long long i = (long long)blockIdx.x * blockDim.x + threadIdx.x;
    if (i >= (long long)RR * EE) return;
    int r = (int)(i / EE);
    atomicAdd(&g_degout[r * NN + src[i]], 1);
    atomicAdd(&g_degin[r * NN + dst[i]], 1);
}

__global__ void rsqrt_kernel() {
    int i = blockIdx.x * blockDim.x + threadIdx.x;
    if (i >= SCAN_N) return;
    g_rdout[i] = rsqrtf(fmaxf((float)g_degout[i], 1.f));
    g_rdin[i]  = rsqrtf(fmaxf((float)g_degin[i], 1.f));
}

__global__ void scan_a_kernel() {
    __shared__ int s[SCAN_BLK];
    int i = blockIdx.x * SCAN_BLK + threadIdx.x;
    s[threadIdx.x] = (i < SCAN_N) ? g_degin[i] : 0;
    __syncthreads();
    for (int d = SCAN_BLK / 2; d > 0; d >>= 1) {
        if (threadIdx.x < d) s[threadIdx.x] += s[threadIdx.x + d];
        __syncthreads();
    }
    if (threadIdx.x == 0) g_bsum[blockIdx.x] = s[0];
}

__global__ void scan_b_kernel() {
    __shared__ int s[1024];
    int t = threadIdx.x;
    s[t] = (t < SCAN_NBLK) ? g_bsum[t] : 0;
    __syncthreads();
    for (int d = 1; d < 1024; d <<= 1) {
        int v = (t >= d) ? s[t - d] : 0;
        __syncthreads();
        s[t] += v;
        __syncthreads();
    }
    if (t < SCAN_NBLK) g_bsum[t] = (t == 0) ? 0 : s[t - 1];
}

__global__ void scan_c_kernel() {
    __shared__ int s[SCAN_BLK];
    int i = blockIdx.x * SCAN_BLK + threadIdx.x;
    int v = (i < SCAN_N) ? g_degin[i] : 0;
    s[threadIdx.x] = v;
    __syncthreads();
    for (int d = 1; d < SCAN_BLK; d <<= 1) {
        int u = (threadIdx.x >= d) ? s[threadIdx.x - d] : 0;
        __syncthreads();
        s[threadIdx.x] += u;
        __syncthreads();
    }
    if (i < SCAN_N) {
        int ex = s[threadIdx.x] - v + g_bsum[blockIdx.x];
        g_off[i] = ex;
        g_cur[i] = ex;
    }
}

__global__ void fill_kernel(const int* __restrict__ src, const int* __restrict__ dst,
                            const float* __restrict__ ew) {
    long long i = (long long)blockIdx.x * blockDim.x + threadIdx.x;
    if (i >= (long long)RR * EE) return;
    int r = (int)(i / EE);
    int s = src[i], d = dst[i];
    float w = ew[i] * g_rdout[r * NN + s] * g_rdin[r * NN + d];
    int p = atomicAdd(&g_cur[r * NN + d], 1);
    g_csr[p] = make_float2(__int_as_float(s), w);
}

// ---------------- fp16-split tensor-core GEMM: Yh = half(h @ W) --------------
// 3-term: ah*bh + ah*bl + al*bh (al*bl dropped, O(2^-22)). m16n16k16 HMMA.
// Block: 64 rows x 128 cols, 8 warps; K chunked by 32.
__global__ __launch_bounds__(256) void gemm_fp16_kernel(
    const float* __restrict__ h, const float* __restrict__ W)
{
    __shared__ __half sAh[64][40], sAl[64][40];      // ldm 40 (mult of 8)
    __shared__ __half sBh[32][136], sBl[32][136];    // ldm 136 (mult of 8)
    __shared__ float  sStage[8][16][20];             // epilogue staging (ldm 20)

    const int row0 = blockIdx.x * 64;
    const int tid = threadIdx.x;
    const int wid = tid >> 5;
    const int lane = tid & 31;
    const int wr = wid & 3;
    const int wc = wid >> 2;

    wmma::fragment<wmma::accumulator, 16, 16, 16, float> acc[4];
#pragma unroll
    for (int i = 0; i < 4; i++) wmma::fill_fragment(acc[i], 0.f);

    for (int kc = 0; kc < DD; kc += 32) {
        // stage A chunk [64 x 32], hi/lo fp16 split
#pragma unroll
        for (int t = tid; t < 64 * 32; t += 256) {
            int rr = t >> 5, kk = t & 31;
            int n = row0 + rr;
            float a = (n < NN) ? h[(size_t)n * DD + kc + kk] : 0.f;
            __half hi = __float2half_rn(a);
            sAh[rr][kk] = hi;
            sAl[rr][kk] = __float2half_rn(a - __half2float(hi));
        }
        // stage B chunk [32 x 128], hi/lo fp16 split
#pragma unroll
        for (int t = tid; t < 32 * 128; t += 256) {
            int rr = t >> 7, j = t & 127;
            float b = W[(size_t)(kc + rr) * DD + j];
            __half hi = __float2half_rn(b);
            sBh[rr][j] = hi;
            sBl[rr][j] = __float2half_rn(b - __half2float(hi));
        }
        __syncthreads();

#pragma unroll
        for (int ks = 0; ks < 2; ks++) {
            wmma::fragment<wmma::matrix_a, 16, 16, 16, __half, wmma::row_major> ah, al;
            wmma::load_matrix_sync(ah, &sAh[wr * 16][ks * 16], 40);
            wmma::load_matrix_sync(al, &sAl[wr * 16][ks * 16], 40);
#pragma unroll
            for (int cg = 0; cg < 4; cg++) {
                int col = wc * 64 + cg * 16;
                wmma::fragment<wmma::matrix_b, 16, 16, 16, __half, wmma::row_major> bh, bl;
                wmma::load_matrix_sync(bh, &sBh[ks * 16][col], 136);
                wmma::load_matrix_sync(bl, &sBl[ks * 16][col], 136);
                wmma::mma_sync(acc[cg], ah, bh, acc[cg]);
                wmma::mma_sync(acc[cg], ah, bl, acc[cg]);
                wmma::mma_sync(acc[cg], al, bh, acc[cg]);
            }
        }
        __syncthreads();
    }

    const int rr = lane >> 1;
    const int cb = (lane & 1) * 8;
#pragma unroll
    for (int cg = 0; cg < 4; cg++) {
        wmma::store_matrix_sync(&sStage[wid][0][0], acc[cg], 20, wmma::mem_row_major);
        __syncwarp();
        const float* sp = &sStage[wid][rr][cb];
        __half2 h0 = __floats2half2_rn(sp[0], sp[1]);
        __half2 h1 = __floats2half2_rn(sp[2], sp[3]);
        __half2 h2 = __floats2half2_rn(sp[4], sp[5]);
        __half2 h3 = __floats2half2_rn(sp[6], sp[7]);
        int grow = row0 + wr * 16 + rr;
        int gcol = wc * 64 + cg * 16 + cb;
        __half2 pack[4] = {h0, h1, h2, h3};
        *(uint4*)(g_Yh + (size_t)grow * DD + gcol) = *(const uint4*)pack;
        __syncwarp();
    }
}

// ---------------- per-relation pull: acc[n] (+)= sum_e Yh[src]*w -------------
// Warp per node; coalesced edge-record load + shfl broadcast (R9 structure).
__global__ __launch_bounds__(256) void pull_r_kernel(int r, int first)
{
    int warp = (blockIdx.x * blockDim.x + threadIdx.x) >> 5;
    int lane = threadIdx.x & 31;
    if (warp >= NN) return;
    int idx = r * NN + warp;
    const float2* eb = g_csr + g_off[idx];
    int cnt = g_degin[idx];
    const int co = lane * 4;

    float4 a0 = make_float4(0.f, 0.f, 0.f, 0.f);

    for (int j = 0; j < cnt; j += 32) {
        int m = cnt - j; if (m > 32) m = 32;
        float2 er = (lane < m) ? eb[j + lane] : make_float2(0.f, 0.f);
        int si = __float_as_int(er.x);
#pragma unroll 8
        for (int k = 0; k < m; k++) {
            int s  = __shfl_sync(0xffffffffu, si, k);
            float w = __shfl_sync(0xffffffffu, er.y, k);
            uint2 rv = *(const uint2*)(g_Yh + (size_t)s * DD + co);
            float2 f0 = __half22float2(*(__half2*)&rv.x);
            float2 f1 = __half22float2(*(__half2*)&rv.y);
            a0.x += f0.x * w; a0.y += f0.y * w; a0.z += f1.x * w; a0.w += f1.y * w;
        }
    }

    float* accp = g_acc + (size_t)warp * DD + co;
    if (!first) {
        float4 old = *(const float4*)accp;
        a0.x += old.x; a0.y += old.y; a0.z += old.z; a0.w += old.w;
    }
    *(float4*)accp = a0;
}

// out[n][j] = relu(acc[n][j] + sum_r b[r][j])
__global__ void bias_relu_kernel(const float* __restrict__ b, float* __restrict__ out) {
    int i = blockIdx.x * blockDim.x + threadIdx.x;
    if (i >= NN * DD) return;
    int j = i & (DD - 1);
    float bs = b[j] + b[DD + j] + b[2 * DD + j] + b[3 * DD + j];
    out[i] = fmaxf(g_acc[i] + bs, 0.f);
}

// ---------------- launch ----------------------------------------------------

extern "C" void kernel_launch(void* const* d_in, const int* in_sizes, int n_in,
                              void* d_out, int out_size)
{
    const float* x   = (const float*)d_in[0];
    const int*   src = (const int*)d_in[1];
    const int*   dst = (const int*)d_in[2];
    const float* ew  = (const float*)d_in[3];
    const float* W1  = (const float*)d_in[4];
    const float* b1  = (const float*)d_in[5];
    const float* W2  = (const float*)d_in[6];
    const float* b2  = (const float*)d_in[7];
    float* out = (float*)d_out;

    const int T = 256;
    const long long RE = (long long)RR * EE;
    const int edge_blocks = (int)((RE + T - 1) / T);

    // ---- setup (graph identical for both layers) ----
    zero_deg_kernel<<<(SCAN_N + T - 1) / T, T>>>();
    deg_kernel<<<edge_blocks, T>>>(src, dst);
    rsqrt_kernel<<<(SCAN_N + T - 1) / T, T>>>();
    scan_a_kernel<<<SCAN_NBLK, SCAN_BLK>>>();
    scan_b_kernel<<<1, 1024>>>();
    scan_c_kernel<<<SCAN_NBLK, SCAN_BLK>>>();
    fill_kernel<<<edge_blocks, T>>>(src, dst, ew);

    const int ggrid = NP / 64;
    const int pull_blocks = (NN * 32 + T - 1) / T;
    const int elem_blocks = (NN * DD + T - 1) / T;

    // ---- layer 1 ----
    for (int r = 0; r < RR; r++) {
        gemm_fp16_kernel<<<ggrid, T>>>(x, W1 + (size_t)r * DD * DD);
        pull_r_kernel<<<pull_blocks, T>>>(r, r == 0);
    }
    bias_relu_kernel<<<elem_blocks, T>>>(b1, g_h1);

    // ---- layer 2 ----
    for (int r = 0; r < RR; r++) {
        gemm_fp16_kernel<<<ggrid, T>>>(g_h1, W2 + (size_t)r * DD * DD);
        pull_r_kernel<<<pull_blocks, T>>>(r, r == 0);
    }
    bias_relu_kernel<<<elem_blocks, T>>>(b2, out);
}